// round 7
// baseline (speedup 1.0000x reference)
#include <cuda_runtime.h>
#include <cuda_fp16.h>
#include <cstdint>

#define NA 10000
#define NE 320000
#define HD 128
#define NR 50
#define NL 6
#define NT 1024
#define CUTR 5.0f
#define PI_F 3.14159265358979f

#define UMINF 0.0067379469990854670966f
#define INVTF ((1.0f - UMINF) / (float)(NT - 1))
#define SCALEF ((float)(NT - 1) / (1.0f - UMINF))

#define F3W 7
#define F3N 10
#define CMN 5
#define NBLK 148

typedef unsigned long long ull;

// ---------------- scratch ----------------
__device__ int    g_cnt[NA];
__device__ int    g_off[NA + 1];
__device__ int    g_cur[NA];
__device__ __align__(16) int2   g_edge[NE];
__device__ float  g_tmp[NE];
__device__ __align__(16) float  g_x[NA * HD];
__device__ __align__(16) float  g_msg[NA * HD];
__device__ __align__(16) __half g_yh[NA * HD];
__device__ __align__(16) float  g_m[NA * HD];
__device__ __align__(16) __half g_tblcf_h[(size_t)NL * NT * HD];
__device__ __align__(16) __half g_tbln_h[(size_t)NT * HD];

__device__ __forceinline__ float silu_f(float x) { return x / (1.0f + __expf(-x)); }

__device__ __forceinline__ ull ffma2(ull a, ull b, ull c) {
    ull d;
    asm("fma.rn.f32x2 %0, %1, %2, %3;" : "=l"(d) : "l"(a), "l"(b), "l"(c));
    return d;
}
__device__ __forceinline__ ull dup2(float a) {
    unsigned u = __float_as_uint(a);
    ull r;
    asm("mov.b64 %0, {%1, %1};" : "=l"(r) : "r"(u));
    return r;
}
__device__ __forceinline__ ull pack2(float a, float b) {
    unsigned ua = __float_as_uint(a), ub = __float_as_uint(b);
    ull r;
    asm("mov.b64 %0, {%1, %2};" : "=l"(r) : "r"(ua), "r"(ub));
    return r;
}
__device__ __forceinline__ float lo32(ull p) { return __uint_as_float((unsigned)p); }
__device__ __forceinline__ float hi32(ull p) { return __uint_as_float((unsigned)(p >> 32)); }

// ================= MEGA SETUP =================
// [0,625) geom | [625,825) embed | [825,889) build_nbr | [889,1081) build_cf
__global__ __launch_bounds__(512, 2)
void mega_setup(const int* __restrict__ ei, const float* __restrict__ pos,
                const int* __restrict__ z, const float* __restrict__ emb,
                const float* __restrict__ nemb,
                const float* __restrict__ means, const float* __restrict__ betas,
                const float* __restrict__ nprojW, const float* __restrict__ nprojB,
                const float* __restrict__ mlpW1, const float* __restrict__ mlpb1,
                const float* __restrict__ mlpW2, const float* __restrict__ mlpb2) {
    extern __shared__ float sh[];
    int b = blockIdx.x;
    int tid = threadIdx.x;
    if (b < 625) {
        int e = b * 512 + tid;
        if (e >= NE) return;
        int s = ei[e], d = ei[NE + e];
        float dx = pos[3 * s + 0] - pos[3 * d + 0];
        float dy = pos[3 * s + 1] - pos[3 * d + 1];
        float dz = pos[3 * s + 2] - pos[3 * d + 2];
        float d2 = dx * dx + dy * dy + dz * dz + 1e-12f;
        if (d2 < CUTR * CUTR) {
            g_tmp[e] = expf(-sqrtf(d2));
            atomicAdd(&g_cnt[d], 1);
        } else g_tmp[e] = -1.f;
    } else if (b < 825) {
        for (int idx = (b - 625) * 512 + tid; idx < NA * HD; idx += 200 * 512) {
            int i = idx >> 7, h = idx & 127;
            int zz = z[i];
            g_x[idx] = emb[(size_t)zz * HD + h];
            g_yh[idx] = __float2half(nemb[(size_t)zz * HD + h]);
        }
    } else if (b < 889) {
        float* sW = sh;
        float* sB = sW + NR * HD;
        float* sMu = sB + HD;
        float* sBe = sMu + 64;
        float* sBuf = sBe + 64;
        for (int i = tid; i < NR * HD; i += 512) sW[i] = nprojW[i];
        if (tid < HD) sB[tid] = nprojB[tid];
        if (tid < NR) { sMu[tid] = means[tid]; sBe[tid] = betas[tid]; }
        __syncthreads();
        int warp = tid >> 5, lane = tid & 31;
        float* sEA = sBuf + warp * NR;
        int t = (b - 825) * 16 + warp;
        float u = UMINF + (float)t * INVTF;
        float d = -logf(u);
        float C = (d < CUTR) ? 0.5f * (cosf(PI_F * d / CUTR) + 1.f) : 0.f;
        for (int r = lane; r < NR; r += 32) {
            float td = u - sMu[r];
            sEA[r] = C * expf(-sBe[r] * td * td);
        }
        __syncwarp();
        float4 acc = make_float4(0.f, 0.f, 0.f, 0.f);
        #pragma unroll 2
        for (int r = 0; r < NR; r++) {
            float4 w = *(float4*)&sW[r * HD + 4 * lane];
            float a = sEA[r];
            acc.x = fmaf(a, w.x, acc.x);
            acc.y = fmaf(a, w.y, acc.y);
            acc.z = fmaf(a, w.z, acc.z);
            acc.w = fmaf(a, w.w, acc.w);
        }
        float4 bv = *(float4*)&sB[4 * lane];
        __half2* p = (__half2*)&g_tbln_h[(size_t)t * HD + 4 * lane];
        p[0] = __floats2half2_rn((acc.x + bv.x) * C, (acc.y + bv.y) * C);
        p[1] = __floats2half2_rn((acc.z + bv.z) * C, (acc.w + bv.w) * C);
    } else {
        int bb = b - 889;
        int l = bb >> 5;
        int blk = bb & 31;
        float* sW1 = sh;
        float* sB1 = sW1 + NR * HD;
        float* sW2 = sB1 + HD;
        float* sB2 = sW2 + HD * HD;
        float* sMu = sB2 + HD;
        float* sBe = sMu + 64;
        float* sBuf = sBe + 64;
        const float* W1 = mlpW1 + (size_t)l * NR * HD;
        const float* W2 = mlpW2 + (size_t)l * HD * HD;
        for (int i = tid; i < NR * HD; i += 512) sW1[i] = W1[i];
        for (int i = tid; i < HD * HD; i += 512) sW2[i] = W2[i];
        if (tid < HD) { sB1[tid] = mlpb1[l * HD + tid]; sB2[tid] = mlpb2[l * HD + tid]; }
        if (tid < NR) { sMu[tid] = means[tid]; sBe[tid] = betas[tid]; }
        __syncthreads();
        int warp = tid >> 5, lane = tid & 31;
        float* sEA = sBuf + warp * 364;
        float* sH1 = sEA + 2 * NR;
        int t0 = (blk * 16 + warp) * 2;
        for (int i = lane; i < 2 * NR; i += 32) {
            int e = i / NR, r = i - e * NR;
            float u = UMINF + (float)(t0 + e) * INVTF;
            float d = -logf(u);
            float C = (d < CUTR) ? 0.5f * (cosf(PI_F * d / CUTR) + 1.f) : 0.f;
            float td = u - sMu[r];
            sEA[i] = C * expf(-sBe[r] * td * td);
        }
        __syncwarp();
        float4 acc[2];
        #pragma unroll
        for (int e = 0; e < 2; e++) acc[e] = make_float4(0.f, 0.f, 0.f, 0.f);
        #pragma unroll 2
        for (int r = 0; r < NR; r++) {
            float4 w = *(float4*)&sW1[r * HD + 4 * lane];
            #pragma unroll
            for (int e = 0; e < 2; e++) {
                float a = sEA[e * NR + r];
                acc[e].x = fmaf(a, w.x, acc[e].x);
                acc[e].y = fmaf(a, w.y, acc[e].y);
                acc[e].z = fmaf(a, w.z, acc[e].z);
                acc[e].w = fmaf(a, w.w, acc[e].w);
            }
        }
        float4 b1v = *(float4*)&sB1[4 * lane];
        #pragma unroll
        for (int e = 0; e < 2; e++) {
            int c0 = e * 132 + 4 * lane;
            sH1[c0 + 0] = silu_f(acc[e].x + b1v.x);
            sH1[c0 + 1] = silu_f(acc[e].y + b1v.y);
            sH1[c0 + 2] = silu_f(acc[e].z + b1v.z);
            sH1[c0 + 3] = silu_f(acc[e].w + b1v.w);
            acc[e] = make_float4(0.f, 0.f, 0.f, 0.f);
        }
        __syncwarp();
        #pragma unroll 2
        for (int r = 0; r < HD; r++) {
            float4 w = *(float4*)&sW2[r * HD + 4 * lane];
            #pragma unroll
            for (int e = 0; e < 2; e++) {
                float a = sH1[e * 132 + r];
                acc[e].x = fmaf(a, w.x, acc[e].x);
                acc[e].y = fmaf(a, w.y, acc[e].y);
                acc[e].z = fmaf(a, w.z, acc[e].z);
                acc[e].w = fmaf(a, w.w, acc[e].w);
            }
        }
        float4 b2v = *(float4*)&sB2[4 * lane];
        #pragma unroll
        for (int e = 0; e < 2; e++) {
            int t = t0 + e;
            float u = UMINF + (float)t * INVTF;
            float d = -logf(u);
            float C = (d < CUTR) ? 0.5f * (cosf(PI_F * d / CUTR) + 1.f) : 0.f;
            __half2* p = (__half2*)&g_tblcf_h[((size_t)l * NT + t) * HD + 4 * lane];
            p[0] = __floats2half2_rn((acc[e].x + b2v.x) * C, (acc[e].y + b2v.y) * C);
            p[1] = __floats2half2_rn((acc[e].z + b2v.z) * C, (acc[e].w + b2v.w) * C);
        }
    }
}

// ---------------- scan ----------------
__global__ void scan_kernel() {
    __shared__ int sh[1024];
    int tid = threadIdx.x;
    int base = tid * 10;
    int loc[10];
    int sum = 0;
    #pragma unroll
    for (int k = 0; k < 10; k++) {
        int i = base + k;
        int c = (i < NA) ? g_cnt[i] : 0;
        loc[k] = sum; sum += c;
    }
    sh[tid] = sum;
    __syncthreads();
    for (int off = 1; off < 1024; off <<= 1) {
        int v = 0;
        if (tid >= off) v = sh[tid - off];
        __syncthreads();
        sh[tid] += v;
        __syncthreads();
    }
    int pre = (tid == 0) ? 0 : sh[tid - 1];
    #pragma unroll
    for (int k = 0; k < 10; k++) {
        int i = base + k;
        if (i < NA) { g_off[i] = pre + loc[k]; g_cur[i] = pre + loc[k]; }
    }
    if (tid == 1023) g_off[NA] = sh[1023];
}

// ---------------- CSR fill ----------------
__global__ __launch_bounds__(512)
void geom_fill(const int* __restrict__ ei) {
    int e = blockIdx.x * 512 + threadIdx.x;
    if (e >= NE) return;
    float u = g_tmp[e];
    if (u >= 0.f) {
        int d = ei[NE + e];
        int j = atomicAdd(&g_cur[d], 1);
        g_edge[j] = make_int2(ei[e], __float_as_int(u));
    }
}

// ---------------- scatter v2: smem metadata + 4 chains + hfma2 ----------------
__device__ __forceinline__ void edge_fast(int4 mt, int lane,
        const __half* __restrict__ TBL, const __half* __restrict__ Y, float4& acc) {
    const uint2* rp = (const uint2*)TBL + mt.y + lane;
    uint2 h0 = __ldg(rp);
    uint2 h1 = __ldg(rp + 32);
    uint2 hy = __ldg((const uint2*)Y + mt.x + lane);
    __half2 fr2 = *(const __half2*)&mt.z;
    __half2 A0 = *(__half2*)&h0.x, A1 = *(__half2*)&h0.y;
    __half2 B0 = *(__half2*)&h1.x, B1 = *(__half2*)&h1.y;
    __half2 wa = __hfma2(fr2, __hsub2(B0, A0), A0);
    __half2 wb = __hfma2(fr2, __hsub2(B1, A1), A1);
    __half2 pa = __hmul2(wa, *(__half2*)&hy.x);
    __half2 pb = __hmul2(wb, *(__half2*)&hy.y);
    float2 fa = __half22float2(pa), fb = __half22float2(pb);
    float g = __int_as_float(mt.w);
    acc.x = fmaf(fa.x, g, acc.x);
    acc.y = fmaf(fa.y, g, acc.y);
    acc.z = fmaf(fb.x, g, acc.z);
    acc.w = fmaf(fb.y, g, acc.w);
}

__device__ __forceinline__ void edge_slow(int j, int n, int lane, int self_mask,
        const __half* __restrict__ TBL, const __half* __restrict__ Y, float4& acc) {
    int2 ed = __ldg(&g_edge[j]);
    float u = __int_as_float(ed.y);
    float tf = fminf(fmaxf((u - UMINF) * SCALEF, 0.f), (float)(NT - 1));
    int ti = (int)tf; if (ti > NT - 2) ti = NT - 2;
    float fr = tf - (float)ti;
    __half2 fh = __float2half2_rn(fr);
    int4 mt = make_int4(ed.x * 32, ti * 32, *(int*)&fh,
                        __float_as_int((self_mask && ed.x == n) ? 0.f : 1.f));
    edge_fast(mt, lane, TBL, Y, acc);
}

__global__ __launch_bounds__(512)
void scatter_kernel(const __half* __restrict__ TBL, const __half* __restrict__ Y,
                    float* __restrict__ M, int self_mask) {
    __shared__ int4 sMeta[16][32];
    int warp = threadIdx.x >> 5, lane = threadIdx.x & 31;
    int n = blockIdx.x * 16 + warp;
    if (n >= NA) return;
    int beg = __ldg(&g_off[n]), end = __ldg(&g_off[n + 1]);
    int cv = min(end - beg, 32);
    if (lane < cv) {
        int2 ed = __ldg(&g_edge[beg + lane]);
        float u = __int_as_float(ed.y);
        float tf = fminf(fmaxf((u - UMINF) * SCALEF, 0.f), (float)(NT - 1));
        int ti = (int)tf; if (ti > NT - 2) ti = NT - 2;
        float fr = tf - (float)ti;
        __half2 fh = __float2half2_rn(fr);
        sMeta[warp][lane] = make_int4(ed.x * 32, ti * 32, *(int*)&fh,
                                      __float_as_int((self_mask && ed.x == n) ? 0.f : 1.f));
    }
    __syncwarp();
    float4 ac0 = make_float4(0.f, 0.f, 0.f, 0.f), ac1 = ac0, ac2 = ac0, ac3 = ac0;
    int e = 0;
    for (; e + 4 <= cv; e += 4) {
        edge_fast(sMeta[warp][e + 0], lane, TBL, Y, ac0);
        edge_fast(sMeta[warp][e + 1], lane, TBL, Y, ac1);
        edge_fast(sMeta[warp][e + 2], lane, TBL, Y, ac2);
        edge_fast(sMeta[warp][e + 3], lane, TBL, Y, ac3);
    }
    for (; e < cv; e++) edge_fast(sMeta[warp][e], lane, TBL, Y, ac0);
    for (int j = beg + 32; j < end; j++) edge_slow(j, n, lane, self_mask, TBL, Y, ac1);
    ac0.x += ac1.x + ac2.x + ac3.x;
    ac0.y += ac1.y + ac2.y + ac3.y;
    ac0.z += ac1.z + ac2.z + ac3.z;
    ac0.w += ac1.w + ac2.w + ac3.w;
    *(float4*)(M + (size_t)n * HD + 4 * lane) = ac0;
}

// ---------- comb_mm: x = [x,msg]@Wc+bc ; y0 = x@W1 (fp16 out) ----------
__global__ __launch_bounds__(224, 1)
void comb_mm(const float* __restrict__ Wc, const float* __restrict__ bc,
             const float* __restrict__ W1) {
    extern __shared__ float sh[];
    float* sWc = sh;
    float* sW1 = sh + 256 * HD;
    __half* sTh = (__half*)(sh + 256 * HD + HD * HD);
    int tid = threadIdx.x;
    for (int i = tid; i < 256 * HD; i += 224) sWc[i] = Wc[i];
    for (int i = tid; i < HD * HD; i += 224) sW1[i] = W1[i];
    __syncthreads();
    int warp = tid >> 5, lane = tid & 31;
    __half* sX = sTh + warp * 1280;
    float4 bcf = __ldg((const float4*)bc + lane);
    ull bca = pack2(bcf.x, bcf.y), bcb = pack2(bcf.z, bcf.w);
    for (int pass = 0; pass < 2; pass++) {
        int gw = blockIdx.x * F3W + warp + pass * (NBLK * F3W);
        int n0 = gw * CMN;
        __syncwarp();
        for (int i = lane; i < CMN * 64; i += 32) {
            int nn = i >> 6, c = i & 63;
            int node = min(n0 + nn, NA - 1);
            float4 v = (c < 32)
                ? __ldg((const float4*)(g_x + (size_t)node * HD) + c)
                : __ldg((const float4*)(g_msg + (size_t)node * HD) + (c - 32));
            __half2 h0 = __floats2half2_rn(v.x, v.y);
            __half2 h1 = __floats2half2_rn(v.z, v.w);
            uint2 st; st.x = *(unsigned*)&h0; st.y = *(unsigned*)&h1;
            ((uint2*)sX)[i] = st;
        }
        __syncwarp();
        ull acc[CMN][2];
        #pragma unroll
        for (int nn = 0; nn < CMN; nn++) { acc[nn][0] = bca; acc[nn][1] = bcb; }
        for (int r2 = 0; r2 < 128; r2++) {
            ulonglong2 w0 = *(ulonglong2*)&sWc[(2 * r2) * HD + 4 * lane];
            ulonglong2 w1 = *(ulonglong2*)&sWc[(2 * r2 + 1) * HD + 4 * lane];
            #pragma unroll
            for (int nn = 0; nn < CMN; nn++) {
                float2 af = __half22float2(((__half2*)sX)[nn * 128 + r2]);
                ull aa = dup2(af.x), ab = dup2(af.y);
                acc[nn][0] = ffma2(aa, w0.x, acc[nn][0]);
                acc[nn][1] = ffma2(aa, w0.y, acc[nn][1]);
                acc[nn][0] = ffma2(ab, w1.x, acc[nn][0]);
                acc[nn][1] = ffma2(ab, w1.y, acc[nn][1]);
            }
        }
        __syncwarp();
        #pragma unroll
        for (int nn = 0; nn < CMN; nn++) {
            int node = n0 + nn;
            float4 v = make_float4(lo32(acc[nn][0]), hi32(acc[nn][0]),
                                   lo32(acc[nn][1]), hi32(acc[nn][1]));
            if (node < NA) *(float4*)&g_x[(size_t)node * HD + 4 * lane] = v;
            ((__half2*)sX)[nn * 64 + 2 * lane] = __floats2half2_rn(v.x, v.y);
            ((__half2*)sX)[nn * 64 + 2 * lane + 1] = __floats2half2_rn(v.z, v.w);
            acc[nn][0] = 0ull; acc[nn][1] = 0ull;
        }
        __syncwarp();
        for (int r2 = 0; r2 < 64; r2++) {
            ulonglong2 w0 = *(ulonglong2*)&sW1[(2 * r2) * HD + 4 * lane];
            ulonglong2 w1 = *(ulonglong2*)&sW1[(2 * r2 + 1) * HD + 4 * lane];
            #pragma unroll
            for (int nn = 0; nn < CMN; nn++) {
                float2 af = __half22float2(((__half2*)sX)[nn * 64 + r2]);
                ull aa = dup2(af.x), ab = dup2(af.y);
                acc[nn][0] = ffma2(aa, w0.x, acc[nn][0]);
                acc[nn][1] = ffma2(aa, w0.y, acc[nn][1]);
                acc[nn][0] = ffma2(ab, w1.x, acc[nn][0]);
                acc[nn][1] = ffma2(ab, w1.y, acc[nn][1]);
            }
        }
        #pragma unroll
        for (int nn = 0; nn < CMN; nn++) {
            int node = n0 + nn;
            if (node >= NA) continue;
            ((__half2*)g_yh)[(size_t)node * 64 + 2 * lane] =
                __floats2half2_rn(lo32(acc[nn][0]), hi32(acc[nn][0]));
            ((__half2*)g_yh)[(size_t)node * 64 + 2 * lane + 1] =
                __floats2half2_rn(lo32(acc[nn][1]), hi32(acc[nn][1]));
        }
    }
}

// ------- fused3: t=silu(M@W2+b2); xn=X+t@WL+bL -> xout; y=xn@W1n -> yout (fp16) -------
__global__ __launch_bounds__(224, 1)
void fused3(const float* __restrict__ M,
            const float* __restrict__ W2, const float* __restrict__ b2,
            const float* __restrict__ WL, const float* __restrict__ bL,
            const float* __restrict__ W1n,
            const float* __restrict__ X,
            float* __restrict__ xout, __half* __restrict__ yout) {
    extern __shared__ float sh[];
    float* sW2 = sh;
    float* sWL = sh + HD * HD;
    float* sW1 = sh + 2 * HD * HD;
    __half* sTh = (__half*)(sh + 3 * HD * HD);
    int tid = threadIdx.x;
    for (int i = tid; i < HD * HD; i += 224) {
        sW2[i] = W2[i];
        sWL[i] = WL[i];
        if (W1n) sW1[i] = W1n[i];
    }
    __syncthreads();
    int warp = tid >> 5, lane = tid & 31;
    __half* sX = sTh + warp * 1280;
    int gw = blockIdx.x * F3W + warp;
    int n0 = gw * F3N;
    float4 b2f = __ldg((const float4*)b2 + lane);
    float4 bLf = __ldg((const float4*)bL + lane);
    ull b2a = pack2(b2f.x, b2f.y), b2b = pack2(b2f.z, b2f.w);
    ull bLa = pack2(bLf.x, bLf.y), bLb = pack2(bLf.z, bLf.w);
    for (int i = lane; i < F3N * 32; i += 32) {
        int nn = i >> 5, c = i & 31;
        int node = min(n0 + nn, NA - 1);
        float4 v = __ldg((const float4*)(M + (size_t)node * HD) + c);
        __half2 h0 = __floats2half2_rn(v.x, v.y);
        __half2 h1 = __floats2half2_rn(v.z, v.w);
        uint2 st; st.x = *(unsigned*)&h0; st.y = *(unsigned*)&h1;
        ((uint2*)sX)[i] = st;
    }
    __syncwarp();
    ull acc[F3N][2];
    #pragma unroll
    for (int nn = 0; nn < F3N; nn++) { acc[nn][0] = b2a; acc[nn][1] = b2b; }
    for (int r2 = 0; r2 < 64; r2++) {
        ulonglong2 w0 = *(ulonglong2*)&sW2[(2 * r2) * HD + 4 * lane];
        ulonglong2 w1 = *(ulonglong2*)&sW2[(2 * r2 + 1) * HD + 4 * lane];
        #pragma unroll
        for (int nn = 0; nn < F3N; nn++) {
            float2 af = __half22float2(((__half2*)sX)[nn * 64 + r2]);
            ull aa = dup2(af.x), ab = dup2(af.y);
            acc[nn][0] = ffma2(aa, w0.x, acc[nn][0]);
            acc[nn][1] = ffma2(aa, w0.y, acc[nn][1]);
            acc[nn][0] = ffma2(ab, w1.x, acc[nn][0]);
            acc[nn][1] = ffma2(ab, w1.y, acc[nn][1]);
        }
    }
    __syncwarp();
    #pragma unroll
    for (int nn = 0; nn < F3N; nn++) {
        float t0 = silu_f(lo32(acc[nn][0])), t1 = silu_f(hi32(acc[nn][0]));
        float t2 = silu_f(lo32(acc[nn][1])), t3 = silu_f(hi32(acc[nn][1]));
        ((__half2*)sX)[nn * 64 + 2 * lane] = __floats2half2_rn(t0, t1);
        ((__half2*)sX)[nn * 64 + 2 * lane + 1] = __floats2half2_rn(t2, t3);
        acc[nn][0] = bLa; acc[nn][1] = bLb;
    }
    __syncwarp();
    for (int r2 = 0; r2 < 64; r2++) {
        ulonglong2 w0 = *(ulonglong2*)&sWL[(2 * r2) * HD + 4 * lane];
        ulonglong2 w1 = *(ulonglong2*)&sWL[(2 * r2 + 1) * HD + 4 * lane];
        #pragma unroll
        for (int nn = 0; nn < F3N; nn++) {
            float2 af = __half22float2(((__half2*)sX)[nn * 64 + r2]);
            ull aa = dup2(af.x), ab = dup2(af.y);
            acc[nn][0] = ffma2(aa, w0.x, acc[nn][0]);
            acc[nn][1] = ffma2(aa, w0.y, acc[nn][1]);
            acc[nn][0] = ffma2(ab, w1.x, acc[nn][0]);
            acc[nn][1] = ffma2(ab, w1.y, acc[nn][1]);
        }
    }
    __syncwarp();
    #pragma unroll
    for (int nn = 0; nn < F3N; nn++) {
        int node = n0 + nn;
        float4 xv = make_float4(0.f, 0.f, 0.f, 0.f);
        if (node < NA) xv = __ldg((const float4*)(X + (size_t)node * HD) + lane);
        float4 v;
        v.x = xv.x + lo32(acc[nn][0]);
        v.y = xv.y + hi32(acc[nn][0]);
        v.z = xv.z + lo32(acc[nn][1]);
        v.w = xv.w + hi32(acc[nn][1]);
        if (node < NA) *(float4*)&xout[(size_t)node * HD + 4 * lane] = v;
        ((__half2*)sX)[nn * 64 + 2 * lane] = __floats2half2_rn(v.x, v.y);
        ((__half2*)sX)[nn * 64 + 2 * lane + 1] = __floats2half2_rn(v.z, v.w);
        acc[nn][0] = 0ull; acc[nn][1] = 0ull;
    }
    if (W1n) {
        __syncwarp();
        for (int r2 = 0; r2 < 64; r2++) {
            ulonglong2 w0 = *(ulonglong2*)&sW1[(2 * r2) * HD + 4 * lane];
            ulonglong2 w1 = *(ulonglong2*)&sW1[(2 * r2 + 1) * HD + 4 * lane];
            #pragma unroll
            for (int nn = 0; nn < F3N; nn++) {
                float2 af = __half22float2(((__half2*)sX)[nn * 64 + r2]);
                ull aa = dup2(af.x), ab = dup2(af.y);
                acc[nn][0] = ffma2(aa, w0.x, acc[nn][0]);
                acc[nn][1] = ffma2(aa, w0.y, acc[nn][1]);
                acc[nn][0] = ffma2(ab, w1.x, acc[nn][0]);
                acc[nn][1] = ffma2(ab, w1.y, acc[nn][1]);
            }
        }
        #pragma unroll
        for (int nn = 0; nn < F3N; nn++) {
            int node = n0 + nn;
            if (node >= NA) continue;
            ((__half2*)yout)[(size_t)node * 64 + 2 * lane] =
                __floats2half2_rn(lo32(acc[nn][0]), hi32(acc[nn][0]));
            ((__half2*)yout)[(size_t)node * 64 + 2 * lane + 1] =
                __floats2half2_rn(lo32(acc[nn][1]), hi32(acc[nn][1]));
        }
    }
}

// ---------------- launcher ----------------
extern "C" void kernel_launch(void* const* d_in, const int* in_sizes, int n_in,
                              void* d_out, int out_size) {
    const int*   z      = (const int*)d_in[0];
    const float* pos    = (const float*)d_in[1];
    const int*   ei     = (const int*)d_in[3];
    const float* emb    = (const float*)d_in[4];
    const float* nemb   = (const float*)d_in[5];
    const float* nprojW = (const float*)d_in[6];
    const float* nprojB = (const float*)d_in[7];
    const float* ncombW = (const float*)d_in[8];
    const float* ncombB = (const float*)d_in[9];
    const float* means  = (const float*)d_in[10];
    const float* betas  = (const float*)d_in[11];
    const float* mlpW1  = (const float*)d_in[12];
    const float* mlpb1  = (const float*)d_in[13];
    const float* mlpW2  = (const float*)d_in[14];
    const float* mlpb2  = (const float*)d_in[15];
    const float* convW1 = (const float*)d_in[16];
    const float* convW2 = (const float*)d_in[17];
    const float* convb2 = (const float*)d_in[18];
    const float* linW   = (const float*)d_in[19];
    const float* linb   = (const float*)d_in[20];
    float* out = (float*)d_out;

    void *p_cnt, *p_x, *p_yh, *p_m, *p_msg, *p_tc, *p_tn;
    cudaGetSymbolAddress(&p_cnt, g_cnt);
    cudaGetSymbolAddress(&p_x, g_x);
    cudaGetSymbolAddress(&p_yh, g_yh);
    cudaGetSymbolAddress(&p_m, g_m);
    cudaGetSymbolAddress(&p_msg, g_msg);
    cudaGetSymbolAddress(&p_tc, g_tblcf_h);
    cudaGetSymbolAddress(&p_tn, g_tbln_h);
    float* px = (float*)p_x;
    __half* pyh = (__half*)p_yh;
    float* pm = (float*)p_m;
    float* pmsg = (float*)p_msg;
    __half* ptc = (__half*)p_tc;
    __half* ptn = (__half*)p_tn;

    size_t sh_mega = (size_t)28992 * sizeof(float);
    size_t sh_cm   = (size_t)(256 * HD + HD * HD) * sizeof(float) + 17920;
    size_t sh_f3   = (size_t)(3 * HD * HD) * sizeof(float) + 17920;
    cudaFuncSetAttribute(mega_setup, cudaFuncAttributeMaxDynamicSharedMemorySize, (int)sh_mega);
    cudaFuncSetAttribute(comb_mm,    cudaFuncAttributeMaxDynamicSharedMemorySize, (int)sh_cm);
    cudaFuncSetAttribute(fused3,     cudaFuncAttributeMaxDynamicSharedMemorySize, (int)sh_f3);

    cudaMemsetAsync(p_cnt, 0, NA * sizeof(int));
    mega_setup<<<1081, 512, sh_mega>>>(ei, pos, z, emb, nemb, means, betas,
                                       nprojW, nprojB, mlpW1, mlpb1, mlpW2, mlpb2);
    scan_kernel<<<1, 1024>>>();
    geom_fill<<<625, 512>>>(ei);
    scatter_kernel<<<625, 512>>>(ptn, pyh, pmsg, 1);
    comb_mm<<<NBLK, 224, sh_cm>>>(ncombW, ncombB, convW1);

    for (int l = 0; l < NL; l++) {
        scatter_kernel<<<625, 512>>>(ptc + (size_t)l * NT * HD, pyh, pm, 0);
        float* dest = (l == NL - 1) ? out : px;
        const float* W1n = (l == NL - 1) ? nullptr : (convW1 + (size_t)(l + 1) * HD * HD);
        fused3<<<NBLK, 224, sh_f3>>>(pm, convW2 + (size_t)l * HD * HD,
                                     convb2 + (size_t)l * HD,
                                     linW + (size_t)l * HD * HD,
                                     linb + (size_t)l * HD,
                                     W1n, px, dest, pyh);
    }
}

// round 8
// speedup vs baseline: 1.4456x; 1.4456x over previous
#include <cuda_runtime.h>
#include <cuda_fp16.h>
#include <cstdint>

#define NA 10000
#define NE 320000
#define HD 128
#define NR 50
#define NL 6
#define NT 1024
#define CUTR 5.0f
#define PI_F 3.14159265358979f

#define UMINF 0.0067379469990854670966f
#define INVTF ((1.0f - UMINF) / (float)(NT - 1))
#define SCALEF ((float)(NT - 1) / (1.0f - UMINF))

#define NBLK79 79          // ceil(NA/128)
#define PH 136             // padded halves per 128-col row (272B)
#define PH2 264            // padded halves per 256-col row (528B)
#define WSLOT 17408        // halves per padded 128x128 weight

typedef unsigned long long ull;

// ---------------- scratch ----------------
__device__ int    g_cnt[NA];
__device__ int    g_off[NA + 1];
__device__ int    g_cur[NA];
__device__ __align__(16) int2   g_edge[NE];
__device__ float  g_tmp[NE];
__device__ __align__(16) float  g_x[NA * HD];
__device__ __align__(16) float  g_msg[NA * HD];
__device__ __align__(16) __half g_yh[NA * HD];
__device__ __align__(16) float  g_m[NA * HD];
__device__ __align__(16) __half g_tblcf_h[(size_t)NL * NT * HD];
__device__ __align__(16) __half g_tbln_h[(size_t)NT * HD];
__device__ __align__(16) __half g_wt[(size_t)18 * WSLOT];    // padded fp16 weights (slot17 = convW1[0])
__device__ __align__(16) __half g_wc[(size_t)256 * PH];      // padded fp16 ncombW

__device__ __forceinline__ float silu_f(float x) { return x / (1.0f + __expf(-x)); }

__device__ __forceinline__ uint32_t smem_u32(const void* p) {
    uint32_t a;
    asm("{ .reg .u64 t; cvta.to.shared.u64 t, %1; cvt.u32.u64 %0, t; }" : "=r"(a) : "l"(p));
    return a;
}

// ================= MEGA SETUP =================
// [0,625) geom | [625,825) embed | [825,889) build_nbr | [889,1081) build_cf
// [1081,1099) g_wt pad-convert | [1099,1101) g_wc pad-convert
__global__ __launch_bounds__(512, 2)
void mega_setup(const int* __restrict__ ei, const float* __restrict__ pos,
                const int* __restrict__ z, const float* __restrict__ emb,
                const float* __restrict__ nemb,
                const float* __restrict__ means, const float* __restrict__ betas,
                const float* __restrict__ nprojW, const float* __restrict__ nprojB,
                const float* __restrict__ mlpW1, const float* __restrict__ mlpb1,
                const float* __restrict__ mlpW2, const float* __restrict__ mlpb2,
                const float* __restrict__ convW1, const float* __restrict__ convW2,
                const float* __restrict__ linW, const float* __restrict__ ncombW) {
    extern __shared__ float sh[];
    int b = blockIdx.x;
    int tid = threadIdx.x;
    if (b < 625) {
        int e = b * 512 + tid;
        if (e >= NE) return;
        int s = ei[e], d = ei[NE + e];
        float dx = pos[3 * s + 0] - pos[3 * d + 0];
        float dy = pos[3 * s + 1] - pos[3 * d + 1];
        float dz = pos[3 * s + 2] - pos[3 * d + 2];
        float d2 = dx * dx + dy * dy + dz * dz + 1e-12f;
        if (d2 < CUTR * CUTR) {
            g_tmp[e] = expf(-sqrtf(d2));
            atomicAdd(&g_cnt[d], 1);
        } else g_tmp[e] = -1.f;
    } else if (b < 825) {
        for (int idx = (b - 625) * 512 + tid; idx < NA * HD; idx += 200 * 512) {
            int i = idx >> 7, h = idx & 127;
            int zz = z[i];
            g_x[idx] = emb[(size_t)zz * HD + h];
            g_yh[idx] = __float2half(nemb[(size_t)zz * HD + h]);
        }
    } else if (b < 889) {
        float* sW = sh;
        float* sB = sW + NR * HD;
        float* sMu = sB + HD;
        float* sBe = sMu + 64;
        float* sBuf = sBe + 64;
        for (int i = tid; i < NR * HD; i += 512) sW[i] = nprojW[i];
        if (tid < HD) sB[tid] = nprojB[tid];
        if (tid < NR) { sMu[tid] = means[tid]; sBe[tid] = betas[tid]; }
        __syncthreads();
        int warp = tid >> 5, lane = tid & 31;
        float* sEA = sBuf + warp * NR;
        int t = (b - 825) * 16 + warp;
        float u = UMINF + (float)t * INVTF;
        float d = -logf(u);
        float C = (d < CUTR) ? 0.5f * (cosf(PI_F * d / CUTR) + 1.f) : 0.f;
        for (int r = lane; r < NR; r += 32) {
            float td = u - sMu[r];
            sEA[r] = C * expf(-sBe[r] * td * td);
        }
        __syncwarp();
        float4 acc = make_float4(0.f, 0.f, 0.f, 0.f);
        #pragma unroll 2
        for (int r = 0; r < NR; r++) {
            float4 w = *(float4*)&sW[r * HD + 4 * lane];
            float a = sEA[r];
            acc.x = fmaf(a, w.x, acc.x);
            acc.y = fmaf(a, w.y, acc.y);
            acc.z = fmaf(a, w.z, acc.z);
            acc.w = fmaf(a, w.w, acc.w);
        }
        float4 bv = *(float4*)&sB[4 * lane];
        __half2* p = (__half2*)&g_tbln_h[(size_t)t * HD + 4 * lane];
        p[0] = __floats2half2_rn((acc.x + bv.x) * C, (acc.y + bv.y) * C);
        p[1] = __floats2half2_rn((acc.z + bv.z) * C, (acc.w + bv.w) * C);
    } else if (b < 1081) {
        int bb = b - 889;
        int l = bb >> 5;
        int blk = bb & 31;
        float* sW1 = sh;
        float* sB1 = sW1 + NR * HD;
        float* sW2 = sB1 + HD;
        float* sB2 = sW2 + HD * HD;
        float* sMu = sB2 + HD;
        float* sBe = sMu + 64;
        float* sBuf = sBe + 64;
        const float* W1 = mlpW1 + (size_t)l * NR * HD;
        const float* W2 = mlpW2 + (size_t)l * HD * HD;
        for (int i = tid; i < NR * HD; i += 512) sW1[i] = W1[i];
        for (int i = tid; i < HD * HD; i += 512) sW2[i] = W2[i];
        if (tid < HD) { sB1[tid] = mlpb1[l * HD + tid]; sB2[tid] = mlpb2[l * HD + tid]; }
        if (tid < NR) { sMu[tid] = means[tid]; sBe[tid] = betas[tid]; }
        __syncthreads();
        int warp = tid >> 5, lane = tid & 31;
        float* sEA = sBuf + warp * 364;
        float* sH1 = sEA + 2 * NR;
        int t0 = (blk * 16 + warp) * 2;
        for (int i = lane; i < 2 * NR; i += 32) {
            int e = i / NR, r = i - e * NR;
            float u = UMINF + (float)(t0 + e) * INVTF;
            float d = -logf(u);
            float C = (d < CUTR) ? 0.5f * (cosf(PI_F * d / CUTR) + 1.f) : 0.f;
            float td = u - sMu[r];
            sEA[i] = C * expf(-sBe[r] * td * td);
        }
        __syncwarp();
        float4 acc[2];
        #pragma unroll
        for (int e = 0; e < 2; e++) acc[e] = make_float4(0.f, 0.f, 0.f, 0.f);
        #pragma unroll 2
        for (int r = 0; r < NR; r++) {
            float4 w = *(float4*)&sW1[r * HD + 4 * lane];
            #pragma unroll
            for (int e = 0; e < 2; e++) {
                float a = sEA[e * NR + r];
                acc[e].x = fmaf(a, w.x, acc[e].x);
                acc[e].y = fmaf(a, w.y, acc[e].y);
                acc[e].z = fmaf(a, w.z, acc[e].z);
                acc[e].w = fmaf(a, w.w, acc[e].w);
            }
        }
        float4 b1v = *(float4*)&sB1[4 * lane];
        #pragma unroll
        for (int e = 0; e < 2; e++) {
            int c0 = e * 132 + 4 * lane;
            sH1[c0 + 0] = silu_f(acc[e].x + b1v.x);
            sH1[c0 + 1] = silu_f(acc[e].y + b1v.y);
            sH1[c0 + 2] = silu_f(acc[e].z + b1v.z);
            sH1[c0 + 3] = silu_f(acc[e].w + b1v.w);
            acc[e] = make_float4(0.f, 0.f, 0.f, 0.f);
        }
        __syncwarp();
        #pragma unroll 2
        for (int r = 0; r < HD; r++) {
            float4 w = *(float4*)&sW2[r * HD + 4 * lane];
            #pragma unroll
            for (int e = 0; e < 2; e++) {
                float a = sH1[e * 132 + r];
                acc[e].x = fmaf(a, w.x, acc[e].x);
                acc[e].y = fmaf(a, w.y, acc[e].y);
                acc[e].z = fmaf(a, w.z, acc[e].z);
                acc[e].w = fmaf(a, w.w, acc[e].w);
            }
        }
        float4 b2v = *(float4*)&sB2[4 * lane];
        #pragma unroll
        for (int e = 0; e < 2; e++) {
            int t = t0 + e;
            float u = UMINF + (float)t * INVTF;
            float d = -logf(u);
            float C = (d < CUTR) ? 0.5f * (cosf(PI_F * d / CUTR) + 1.f) : 0.f;
            __half2* p = (__half2*)&g_tblcf_h[((size_t)l * NT + t) * HD + 4 * lane];
            p[0] = __floats2half2_rn((acc[e].x + b2v.x) * C, (acc[e].y + b2v.y) * C);
            p[1] = __floats2half2_rn((acc[e].z + b2v.z) * C, (acc[e].w + b2v.w) * C);
        }
    } else if (b < 1099) {
        // ---- pad-convert one 128x128 weight matrix to fp16, row stride PH ----
        int mi = b - 1081;   // 0..17
        const float* src;
        if (mi == 17) src = convW1;                       // convW1[0]
        else {
            int l = mi / 3, j = mi % 3;
            src = (j == 0) ? convW2 + (size_t)l * 16384
                : (j == 1) ? linW + (size_t)l * 16384
                           : convW1 + (size_t)(l + 1) * 16384;
        }
        __half* dst = g_wt + (size_t)mi * WSLOT;
        for (int idx = tid; idx < 16384; idx += 512) {
            int k = idx >> 7, n = idx & 127;
            dst[k * PH + n] = __float2half(src[idx]);
        }
    } else {
        // ---- pad-convert ncombW (256x128) ----
        int halfsel = b - 1099;
        for (int i = tid; i < 16384; i += 512) {
            int idx = halfsel * 16384 + i;
            int k = idx >> 7, n = idx & 127;
            g_wc[k * PH + n] = __float2half(ncombW[idx]);
        }
    }
}

// ---------------- scan ----------------
__global__ void scan_kernel() {
    __shared__ int sh[1024];
    int tid = threadIdx.x;
    int base = tid * 10;
    int loc[10];
    int sum = 0;
    #pragma unroll
    for (int k = 0; k < 10; k++) {
        int i = base + k;
        int c = (i < NA) ? g_cnt[i] : 0;
        loc[k] = sum; sum += c;
    }
    sh[tid] = sum;
    __syncthreads();
    for (int off = 1; off < 1024; off <<= 1) {
        int v = 0;
        if (tid >= off) v = sh[tid - off];
        __syncthreads();
        sh[tid] += v;
        __syncthreads();
    }
    int pre = (tid == 0) ? 0 : sh[tid - 1];
    #pragma unroll
    for (int k = 0; k < 10; k++) {
        int i = base + k;
        if (i < NA) { g_off[i] = pre + loc[k]; g_cur[i] = pre + loc[k]; }
    }
    if (tid == 1023) g_off[NA] = sh[1023];
}

// ---------------- CSR fill ----------------
__global__ __launch_bounds__(512)
void geom_fill(const int* __restrict__ ei) {
    int e = blockIdx.x * 512 + threadIdx.x;
    if (e >= NE) return;
    float u = g_tmp[e];
    if (u >= 0.f) {
        int d = ei[NE + e];
        int j = atomicAdd(&g_cur[d], 1);
        g_edge[j] = make_int2(ei[e], __float_as_int(u));
    }
}

// ---------------- scatter (round-4 version: simple, 2 chains) ----------------
__device__ __forceinline__ void edge_acc(int j, int n, int lane, int self_mask,
                                         const __half* __restrict__ TBL,
                                         const __half* __restrict__ Y, float4& acc) {
    int2 ed = __ldg(&g_edge[j]);
    int s = ed.x;
    float u = __int_as_float(ed.y);
    float tf = (u - UMINF) * SCALEF;
    tf = fminf(fmaxf(tf, 0.f), (float)(NT - 1));
    int ti = (int)tf;
    if (ti > NT - 2) ti = NT - 2;
    float fr = tf - (float)ti;
    const uint2* r0 = (const uint2*)TBL + (size_t)ti * 32 + lane;
    uint2 h0 = __ldg(r0);
    uint2 h1 = __ldg(r0 + 32);
    uint2 hy = __ldg((const uint2*)Y + (size_t)s * 32 + lane);
    float2 a0 = __half22float2(*(__half2*)&h0.x);
    float2 a1 = __half22float2(*(__half2*)&h0.y);
    float2 b0 = __half22float2(*(__half2*)&h1.x);
    float2 b1 = __half22float2(*(__half2*)&h1.y);
    float2 y0 = __half22float2(*(__half2*)&hy.x);
    float2 y1 = __half22float2(*(__half2*)&hy.y);
    float g = (self_mask && (s == n)) ? 0.f : 1.f;
    float wx = fmaf(fr, b0.x - a0.x, a0.x) * g;
    float wy = fmaf(fr, b0.y - a0.y, a0.y) * g;
    float wz = fmaf(fr, b1.x - a1.x, a1.x) * g;
    float ww = fmaf(fr, b1.y - a1.y, a1.y) * g;
    acc.x = fmaf(y0.x, wx, acc.x);
    acc.y = fmaf(y0.y, wy, acc.y);
    acc.z = fmaf(y1.x, wz, acc.z);
    acc.w = fmaf(y1.y, ww, acc.w);
}

__global__ __launch_bounds__(512)
void scatter_kernel(const __half* __restrict__ TBL, const __half* __restrict__ Y,
                    float* __restrict__ M, int self_mask) {
    int warp = threadIdx.x >> 5, lane = threadIdx.x & 31;
    int n = blockIdx.x * 16 + warp;
    if (n >= NA) return;
    int beg = __ldg(&g_off[n]), end = __ldg(&g_off[n + 1]);
    float4 a0 = make_float4(0.f, 0.f, 0.f, 0.f);
    float4 a1 = make_float4(0.f, 0.f, 0.f, 0.f);
    int j = beg;
    for (; j + 1 < end; j += 2) {
        edge_acc(j, n, lane, self_mask, TBL, Y, a0);
        edge_acc(j + 1, n, lane, self_mask, TBL, Y, a1);
    }
    if (j < end) edge_acc(j, n, lane, self_mask, TBL, Y, a0);
    a0.x += a1.x; a0.y += a1.y; a0.z += a1.z; a0.w += a1.w;
    *(float4*)(M + (size_t)n * HD + 4 * lane) = a0;
}

// ================= mma.sync building blocks =================
// One warp computes C[16 x 128] = A[16 x K] @ W[K x 128] with m16n8k16 HMMA.
// A in smem row-major fp16, row stride astride bytes; W row stride 272B.
__device__ __forceinline__ void mma_gemm(uint32_t aBase, int ksteps, uint32_t wBase, float* c) {
    #pragma unroll 2
    for (int k = 0; k < ksteps; k++) {
        uint32_t a0, a1, a2, a3;
        asm volatile("ldmatrix.sync.aligned.m8n8.x4.shared.b16 {%0,%1,%2,%3}, [%4];"
            : "=r"(a0), "=r"(a1), "=r"(a2), "=r"(a3) : "r"(aBase + k * 32));
        #pragma unroll
        for (int nbp = 0; nbp < 8; nbp++) {
            uint32_t b0, b1, b2r, b3;
            asm volatile("ldmatrix.sync.aligned.m8n8.x4.trans.shared.b16 {%0,%1,%2,%3}, [%4];"
                : "=r"(b0), "=r"(b1), "=r"(b2r), "=r"(b3)
                : "r"(wBase + k * (16 * 272) + nbp * 32));
            float* cp = c + nbp * 8;
            asm volatile("mma.sync.aligned.m16n8k16.row.col.f32.f16.f16.f32 "
                "{%0,%1,%2,%3}, {%4,%5,%6,%7}, {%8,%9}, {%0,%1,%2,%3};"
                : "+f"(cp[0]), "+f"(cp[1]), "+f"(cp[2]), "+f"(cp[3])
                : "r"(a0), "r"(a1), "r"(a2), "r"(a3), "r"(b0), "r"(b1));
            asm volatile("mma.sync.aligned.m16n8k16.row.col.f32.f16.f16.f32 "
                "{%0,%1,%2,%3}, {%4,%5,%6,%7}, {%8,%9}, {%0,%1,%2,%3};"
                : "+f"(cp[4]), "+f"(cp[5]), "+f"(cp[6]), "+f"(cp[7])
                : "r"(a0), "r"(a1), "r"(a2), "r"(a3), "r"(b2r), "r"(b3));
        }
    }
}

// ================= fused3 via mma.sync =================
// smem: A tile 128 x 272B = 34816 | weights 3 x 34816 at 34816 | bias 256 f32 at 139264
__global__ __launch_bounds__(256, 1)
void fused3_mma(const float* __restrict__ M, const __half* __restrict__ WT,
                const float* __restrict__ b2, const float* __restrict__ bL,
                const float* __restrict__ X,
                float* __restrict__ xout, __half* __restrict__ yout, int has3) {
    extern __shared__ char smc[];
    uint32_t sb = smem_u32(smc);
    float* sBias = (float*)(smc + 139264);
    int tid = threadIdx.x, lane = tid & 31, warp = tid >> 5;
    int nw = has3 ? 3 : 2;
    {
        const uint4* ws = (const uint4*)WT;
        uint4* wd = (uint4*)(smc + 34816);
        for (int i = tid; i < nw * 2176; i += 256) wd[i] = ws[i];
    }
    if (tid < 128) { sBias[tid] = b2[tid]; sBias[128 + tid] = bL[tid]; }
    {   // stage A: M (f32) -> fp16 padded
        int row = tid >> 1, sel = tid & 1;
        int node = min(blockIdx.x * 128 + row, NA - 1);
        const float4* src = (const float4*)(M + (size_t)node * HD) + sel * 16;
        uint4* dst = (uint4*)(smc + row * 272 + sel * 128);
        #pragma unroll
        for (int i = 0; i < 8; i++) {
            float4 v0 = __ldg(src + 2 * i), v1 = __ldg(src + 2 * i + 1);
            __half2 h0 = __floats2half2_rn(v0.x, v0.y);
            __half2 h1 = __floats2half2_rn(v0.z, v0.w);
            __half2 h2 = __floats2half2_rn(v1.x, v1.y);
            __half2 h3 = __floats2half2_rn(v1.z, v1.w);
            uint4 st;
            st.x = *(unsigned*)&h0; st.y = *(unsigned*)&h1;
            st.z = *(unsigned*)&h2; st.w = *(unsigned*)&h3;
            dst[i] = st;
        }
    }
    __syncthreads();

    int r0 = warp * 16;
    uint32_t aBase = sb + (r0 + (lane & 15)) * 272 + (lane >> 4) * 16;
    uint32_t bOff = ((lane & 7) + ((lane >> 3) & 1) * 8) * 272 + (lane >> 4) * 16;
    int cx = (lane & 3) * 2;
    int rtl = r0 + (lane >> 2);            // local top row
    int nodeT = blockIdx.x * 128 + rtl;
    int nodeB = nodeT + 8;
    int nT = min(nodeT, NA - 1), nB = min(nodeB, NA - 1);
    float c[64];

    // ---- stage 1: silu(M @ W2 + b2) -> sA ----
    #pragma unroll
    for (int nb = 0; nb < 16; nb++) {
        float bx0 = sBias[nb * 8 + cx], bx1 = sBias[nb * 8 + cx + 1];
        c[nb * 4 + 0] = bx0; c[nb * 4 + 1] = bx1; c[nb * 4 + 2] = bx0; c[nb * 4 + 3] = bx1;
    }
    mma_gemm(aBase, 8, sb + 34816 + bOff, c);
    __syncwarp();
    #pragma unroll
    for (int nb = 0; nb < 16; nb++) {
        int col = nb * 8 + cx;
        *(__half2*)(smc + rtl * 272 + col * 2) =
            __floats2half2_rn(silu_f(c[nb * 4 + 0]), silu_f(c[nb * 4 + 1]));
        *(__half2*)(smc + (rtl + 8) * 272 + col * 2) =
            __floats2half2_rn(silu_f(c[nb * 4 + 2]), silu_f(c[nb * 4 + 3]));
    }
    __syncwarp();

    // ---- stage 2: xn = X + t @ WL + bL -> xout (f32) + sA (fp16) ----
    #pragma unroll
    for (int nb = 0; nb < 16; nb++) {
        float bx0 = sBias[128 + nb * 8 + cx], bx1 = sBias[128 + nb * 8 + cx + 1];
        c[nb * 4 + 0] = bx0; c[nb * 4 + 1] = bx1; c[nb * 4 + 2] = bx0; c[nb * 4 + 3] = bx1;
    }
    mma_gemm(aBase, 8, sb + 34816 + 34816 + bOff, c);
    __syncwarp();
    #pragma unroll
    for (int nb = 0; nb < 16; nb++) {
        int col = nb * 8 + cx;
        float2 xT = *(const float2*)(X + (size_t)nT * HD + col);
        float2 xB = *(const float2*)(X + (size_t)nB * HD + col);
        float vT0 = c[nb * 4 + 0] + xT.x, vT1 = c[nb * 4 + 1] + xT.y;
        float vB0 = c[nb * 4 + 2] + xB.x, vB1 = c[nb * 4 + 3] + xB.y;
        if (nodeT < NA) *(float2*)(xout + (size_t)nodeT * HD + col) = make_float2(vT0, vT1);
        if (nodeB < NA) *(float2*)(xout + (size_t)nodeB * HD + col) = make_float2(vB0, vB1);
        if (has3) {
            *(__half2*)(smc + rtl * 272 + col * 2) = __floats2half2_rn(vT0, vT1);
            *(__half2*)(smc + (rtl + 8) * 272 + col * 2) = __floats2half2_rn(vB0, vB1);
        }
    }
    if (!has3) return;
    __syncwarp();

    // ---- stage 3: y = xn @ W1n -> yout (fp16) ----
    #pragma unroll
    for (int i = 0; i < 64; i++) c[i] = 0.f;
    mma_gemm(aBase, 8, sb + 34816 + 69632 + bOff, c);
    #pragma unroll
    for (int nb = 0; nb < 16; nb++) {
        int col = nb * 8 + cx;
        if (nodeT < NA)
            *(__half2*)(yout + (size_t)nodeT * HD + col) =
                __floats2half2_rn(c[nb * 4 + 0], c[nb * 4 + 1]);
        if (nodeB < NA)
            *(__half2*)(yout + (size_t)nodeB * HD + col) =
                __floats2half2_rn(c[nb * 4 + 2], c[nb * 4 + 3]);
    }
}

// ================= comb via mma.sync =================
// smem: A tile 128 x 528B = 67584 | Wc 256x272B = 69632 at 67584 |
//       W1 at 137216 (34816) | bias 128 f32 at 172032 -> total 172544
__global__ __launch_bounds__(256, 1)
void comb_mma(const __half* __restrict__ Wc, const __half* __restrict__ W1,
              const float* __restrict__ bc) {
    extern __shared__ char smc[];
    uint32_t sb = smem_u32(smc);
    float* sBias = (float*)(smc + 172032);
    int tid = threadIdx.x, lane = tid & 31, warp = tid >> 5;
    {
        const uint4* ws = (const uint4*)Wc;
        uint4* wd = (uint4*)(smc + 67584);
        for (int i = tid; i < 4352; i += 256) wd[i] = ws[i];
        const uint4* w1s = (const uint4*)W1;
        uint4* w1d = (uint4*)(smc + 137216);
        for (int i = tid; i < 2176; i += 256) w1d[i] = w1s[i];
    }
    if (tid < 128) sBias[tid] = bc[tid];
    {   // stage A: [x | msg] f32 -> fp16, row stride 528B
        int row = tid >> 1, sel = tid & 1;
        int node = min(blockIdx.x * 128 + row, NA - 1);
        const float4* src = sel ? (const float4*)(g_msg + (size_t)node * HD)
                                : (const float4*)(g_x + (size_t)node * HD);
        uint4* dst = (uint4*)(smc + row * 528 + sel * 256);
        #pragma unroll
        for (int i = 0; i < 16; i++) {
            float4 v0 = __ldg(src + 2 * i), v1 = __ldg(src + 2 * i + 1);
            __half2 h0 = __floats2half2_rn(v0.x, v0.y);
            __half2 h1 = __floats2half2_rn(v0.z, v0.w);
            __half2 h2 = __floats2half2_rn(v1.x, v1.y);
            __half2 h3 = __floats2half2_rn(v1.z, v1.w);
            uint4 st;
            st.x = *(unsigned*)&h0; st.y = *(unsigned*)&h1;
            st.z = *(unsigned*)&h2; st.w = *(unsigned*)&h3;
            dst[i] = st;
        }
    }
    __syncthreads();

    int r0 = warp * 16;
    uint32_t aBase = sb + (r0 + (lane & 15)) * 528 + (lane >> 4) * 16;
    uint32_t bOff = ((lane & 7) + ((lane >> 3) & 1) * 8) * 272 + (lane >> 4) * 16;
    int cx = (lane & 3) * 2;
    int rtl = r0 + (lane >> 2);
    int nodeT = blockIdx.x * 128 + rtl;
    int nodeB = nodeT + 8;
    float c[64];

    // ---- stage 1: x = [x,msg] @ Wc + bc ----
    #pragma unroll
    for (int nb = 0; nb < 16; nb++) {
        float bx0 = sBias[nb * 8 + cx], bx1 = sBias[nb * 8 + cx + 1];
        c[nb * 4 + 0] = bx0; c[nb * 4 + 1] = bx1; c[nb * 4 + 2] = bx0; c[nb * 4 + 3] = bx1;
    }
    mma_gemm(aBase, 16, sb + 67584 + bOff, c);
    __syncwarp();
    #pragma unroll
    for (int nb = 0; nb < 16; nb++) {
        int col = nb * 8 + cx;
        float vT0 = c[nb * 4 + 0], vT1 = c[nb * 4 + 1];
        float vB0 = c[nb * 4 + 2], vB1 = c[nb * 4 + 3];
        if (nodeT < NA) *(float2*)(g_x + (size_t)nodeT * HD + col) = make_float2(vT0, vT1);
        if (nodeB < NA) *(float2*)(g_x + (size_t)nodeB * HD + col) = make_float2(vB0, vB1);
        *(__half2*)(smc + rtl * 528 + col * 2) = __floats2half2_rn(vT0, vT1);
        *(__half2*)(smc + (rtl + 8) * 528 + col * 2) = __floats2half2_rn(vB0, vB1);
    }
    __syncwarp();

    // ---- stage 2: y0 = x @ convW1[0] -> g_yh ----
    #pragma unroll
    for (int i = 0; i < 64; i++) c[i] = 0.f;
    mma_gemm(aBase, 8, sb + 137216 + bOff, c);
    #pragma unroll
    for (int nb = 0; nb < 16; nb++) {
        int col = nb * 8 + cx;
        if (nodeT < NA)
            *(__half2*)(g_yh + (size_t)nodeT * HD + col) =
                __floats2half2_rn(c[nb * 4 + 0], c[nb * 4 + 1]);
        if (nodeB < NA)
            *(__half2*)(g_yh + (size_t)nodeB * HD + col) =
                __floats2half2_rn(c[nb * 4 + 2], c[nb * 4 + 3]);
    }
}

// ---------------- launcher ----------------
extern "C" void kernel_launch(void* const* d_in, const int* in_sizes, int n_in,
                              void* d_out, int out_size) {
    const int*   z      = (const int*)d_in[0];
    const float* pos    = (const float*)d_in[1];
    const int*   ei     = (const int*)d_in[3];
    const float* emb    = (const float*)d_in[4];
    const float* nemb   = (const float*)d_in[5];
    const float* nprojW = (const float*)d_in[6];
    const float* nprojB = (const float*)d_in[7];
    const float* ncombW = (const float*)d_in[8];
    const float* ncombB = (const float*)d_in[9];
    const float* means  = (const float*)d_in[10];
    const float* betas  = (const float*)d_in[11];
    const float* mlpW1  = (const float*)d_in[12];
    const float* mlpb1  = (const float*)d_in[13];
    const float* mlpW2  = (const float*)d_in[14];
    const float* mlpb2  = (const float*)d_in[15];
    const float* convW1 = (const float*)d_in[16];
    const float* convW2 = (const float*)d_in[17];
    const float* convb2 = (const float*)d_in[18];
    const float* linW   = (const float*)d_in[19];
    const float* linb   = (const float*)d_in[20];
    float* out = (float*)d_out;

    void *p_cnt, *p_x, *p_yh, *p_m, *p_msg, *p_tc, *p_tn, *p_wt, *p_wc;
    cudaGetSymbolAddress(&p_cnt, g_cnt);
    cudaGetSymbolAddress(&p_x, g_x);
    cudaGetSymbolAddress(&p_yh, g_yh);
    cudaGetSymbolAddress(&p_m, g_m);
    cudaGetSymbolAddress(&p_msg, g_msg);
    cudaGetSymbolAddress(&p_tc, g_tblcf_h);
    cudaGetSymbolAddress(&p_tn, g_tbln_h);
    cudaGetSymbolAddress(&p_wt, g_wt);
    cudaGetSymbolAddress(&p_wc, g_wc);
    float* px = (float*)p_x;
    __half* pyh = (__half*)p_yh;
    float* pm = (float*)p_m;
    float* pmsg = (float*)p_msg;
    __half* ptc = (__half*)p_tc;
    __half* ptn = (__half*)p_tn;
    __half* pwt = (__half*)p_wt;
    __half* pwc = (__half*)p_wc;

    size_t sh_mega = (size_t)28992 * sizeof(float);
    size_t sh_f3m  = 140288;
    size_t sh_cmm  = 172544;
    cudaFuncSetAttribute(mega_setup, cudaFuncAttributeMaxDynamicSharedMemorySize, (int)sh_mega);
    cudaFuncSetAttribute(fused3_mma, cudaFuncAttributeMaxDynamicSharedMemorySize, (int)sh_f3m);
    cudaFuncSetAttribute(comb_mma,   cudaFuncAttributeMaxDynamicSharedMemorySize, (int)sh_cmm);

    cudaMemsetAsync(p_cnt, 0, NA * sizeof(int));
    mega_setup<<<1101, 512, sh_mega>>>(ei, pos, z, emb, nemb, means, betas,
                                       nprojW, nprojB, mlpW1, mlpb1, mlpW2, mlpb2,
                                       convW1, convW2, linW, ncombW);
    scan_kernel<<<1, 1024>>>();
    geom_fill<<<625, 512>>>(ei);
    scatter_kernel<<<625, 512>>>(ptn, pyh, pmsg, 1);
    comb_mma<<<NBLK79, 256, sh_cmm>>>(pwc, pwt + (size_t)17 * WSLOT, ncombB);

    for (int l = 0; l < NL; l++) {
        scatter_kernel<<<625, 512>>>(ptc + (size_t)l * NT * HD, pyh, pm, 0);
        float* dest = (l == NL - 1) ? out : px;
        fused3_mma<<<NBLK79, 256, sh_f3m>>>(pm, pwt + (size_t)(l * 3) * WSLOT,
                                            convb2 + (size_t)l * HD,
                                            linb + (size_t)l * HD,
                                            px, dest, pyh, (l < NL - 1) ? 1 : 0);
    }
}

// round 9
// speedup vs baseline: 1.6348x; 1.1309x over previous
#include <cuda_runtime.h>
#include <cuda_fp16.h>
#include <cstdint>

#define NA 10000
#define NE 320000
#define HD 128
#define NR 50
#define NL 6
#define NT 1024
#define CUTR 5.0f
#define PI_F 3.14159265358979f

#define UMINF 0.0067379469990854670966f
#define INVTF ((1.0f - UMINF) / (float)(NT - 1))
#define SCALEF ((float)(NT - 1) / (1.0f - UMINF))

#define NBLK79 79          // ceil(NA/128)
#define PH 136             // padded halves per 128-col row (272B)
#define WSLOT 17408        // halves per padded 128x128 weight

typedef unsigned long long ull;

// ---------------- scratch ----------------
__device__ int    g_cnt[NA];
__device__ int    g_off[NA + 1];
__device__ int    g_cur[NA];
__device__ __align__(16) int2   g_edge[NE];
__device__ float  g_tmp[NE];
__device__ __align__(16) float  g_x[NA * HD];
__device__ __align__(16) float  g_msg[NA * HD];
__device__ __align__(16) __half g_yh[NA * HD];
__device__ __align__(16) float  g_m[NA * HD];
__device__ __align__(16) __half g_tblcf_h[(size_t)NL * NT * HD];
__device__ __align__(16) __half g_tbln_h[(size_t)NT * HD];
__device__ __align__(16) __half g_wt[(size_t)18 * WSLOT];
__device__ __align__(16) __half g_wc[(size_t)256 * PH];

__device__ __forceinline__ float silu_f(float x) { return x / (1.0f + __expf(-x)); }

__device__ __forceinline__ uint32_t smem_u32(const void* p) {
    uint32_t a;
    asm("{ .reg .u64 t; cvta.to.shared.u64 t, %1; cvt.u32.u64 %0, t; }" : "=r"(a) : "l"(p));
    return a;
}

// ================= MEGA SETUP =================
// Heavy blocks FIRST so they start in wave 1:
// [0,192) build_cf | [192,256) build_nbr | [256,274) wt | [274,276) wc |
// [276,476) embed | [476,1101) geom
__global__ __launch_bounds__(512, 2)
void mega_setup(const int* __restrict__ ei, const float* __restrict__ pos,
                const int* __restrict__ z, const float* __restrict__ emb,
                const float* __restrict__ nemb,
                const float* __restrict__ means, const float* __restrict__ betas,
                const float* __restrict__ nprojW, const float* __restrict__ nprojB,
                const float* __restrict__ mlpW1, const float* __restrict__ mlpb1,
                const float* __restrict__ mlpW2, const float* __restrict__ mlpb2,
                const float* __restrict__ convW1, const float* __restrict__ convW2,
                const float* __restrict__ linW, const float* __restrict__ ncombW) {
    extern __shared__ float sh[];
    int b = blockIdx.x;
    int tid = threadIdx.x;
    if (b < 192) {
        // ---- build_cf ----
        int l = b >> 5;
        int blk = b & 31;
        float* sW1 = sh;
        float* sB1 = sW1 + NR * HD;
        float* sW2 = sB1 + HD;
        float* sB2 = sW2 + HD * HD;
        float* sMu = sB2 + HD;
        float* sBe = sMu + 64;
        float* sBuf = sBe + 64;
        const float* W1 = mlpW1 + (size_t)l * NR * HD;
        const float* W2 = mlpW2 + (size_t)l * HD * HD;
        for (int i = tid; i < NR * HD; i += 512) sW1[i] = W1[i];
        for (int i = tid; i < HD * HD; i += 512) sW2[i] = W2[i];
        if (tid < HD) { sB1[tid] = mlpb1[l * HD + tid]; sB2[tid] = mlpb2[l * HD + tid]; }
        if (tid < NR) { sMu[tid] = means[tid]; sBe[tid] = betas[tid]; }
        __syncthreads();
        int warp = tid >> 5, lane = tid & 31;
        float* sEA = sBuf + warp * 364;
        float* sH1 = sEA + 2 * NR;
        int t0 = (blk * 16 + warp) * 2;
        for (int i = lane; i < 2 * NR; i += 32) {
            int e = i / NR, r = i - e * NR;
            float u = UMINF + (float)(t0 + e) * INVTF;
            float d = -logf(u);
            float C = (d < CUTR) ? 0.5f * (cosf(PI_F * d / CUTR) + 1.f) : 0.f;
            float td = u - sMu[r];
            sEA[i] = C * expf(-sBe[r] * td * td);
        }
        __syncwarp();
        float4 acc[2];
        #pragma unroll
        for (int e = 0; e < 2; e++) acc[e] = make_float4(0.f, 0.f, 0.f, 0.f);
        #pragma unroll 2
        for (int r = 0; r < NR; r++) {
            float4 w = *(float4*)&sW1[r * HD + 4 * lane];
            #pragma unroll
            for (int e = 0; e < 2; e++) {
                float a = sEA[e * NR + r];
                acc[e].x = fmaf(a, w.x, acc[e].x);
                acc[e].y = fmaf(a, w.y, acc[e].y);
                acc[e].z = fmaf(a, w.z, acc[e].z);
                acc[e].w = fmaf(a, w.w, acc[e].w);
            }
        }
        float4 b1v = *(float4*)&sB1[4 * lane];
        #pragma unroll
        for (int e = 0; e < 2; e++) {
            int c0 = e * 132 + 4 * lane;
            sH1[c0 + 0] = silu_f(acc[e].x + b1v.x);
            sH1[c0 + 1] = silu_f(acc[e].y + b1v.y);
            sH1[c0 + 2] = silu_f(acc[e].z + b1v.z);
            sH1[c0 + 3] = silu_f(acc[e].w + b1v.w);
            acc[e] = make_float4(0.f, 0.f, 0.f, 0.f);
        }
        __syncwarp();
        #pragma unroll 2
        for (int r = 0; r < HD; r++) {
            float4 w = *(float4*)&sW2[r * HD + 4 * lane];
            #pragma unroll
            for (int e = 0; e < 2; e++) {
                float a = sH1[e * 132 + r];
                acc[e].x = fmaf(a, w.x, acc[e].x);
                acc[e].y = fmaf(a, w.y, acc[e].y);
                acc[e].z = fmaf(a, w.z, acc[e].z);
                acc[e].w = fmaf(a, w.w, acc[e].w);
            }
        }
        float4 b2v = *(float4*)&sB2[4 * lane];
        #pragma unroll
        for (int e = 0; e < 2; e++) {
            int t = t0 + e;
            float u = UMINF + (float)t * INVTF;
            float d = -logf(u);
            float C = (d < CUTR) ? 0.5f * (cosf(PI_F * d / CUTR) + 1.f) : 0.f;
            __half2* p = (__half2*)&g_tblcf_h[((size_t)l * NT + t) * HD + 4 * lane];
            p[0] = __floats2half2_rn((acc[e].x + b2v.x) * C, (acc[e].y + b2v.y) * C);
            p[1] = __floats2half2_rn((acc[e].z + b2v.z) * C, (acc[e].w + b2v.w) * C);
        }
    } else if (b < 256) {
        // ---- build_nbr ----
        float* sW = sh;
        float* sB = sW + NR * HD;
        float* sMu = sB + HD;
        float* sBe = sMu + 64;
        float* sBuf = sBe + 64;
        for (int i = tid; i < NR * HD; i += 512) sW[i] = nprojW[i];
        if (tid < HD) sB[tid] = nprojB[tid];
        if (tid < NR) { sMu[tid] = means[tid]; sBe[tid] = betas[tid]; }
        __syncthreads();
        int warp = tid >> 5, lane = tid & 31;
        float* sEA = sBuf + warp * NR;
        int t = (b - 192) * 16 + warp;
        float u = UMINF + (float)t * INVTF;
        float d = -logf(u);
        float C = (d < CUTR) ? 0.5f * (cosf(PI_F * d / CUTR) + 1.f) : 0.f;
        for (int r = lane; r < NR; r += 32) {
            float td = u - sMu[r];
            sEA[r] = C * expf(-sBe[r] * td * td);
        }
        __syncwarp();
        float4 acc = make_float4(0.f, 0.f, 0.f, 0.f);
        #pragma unroll 2
        for (int r = 0; r < NR; r++) {
            float4 w = *(float4*)&sW[r * HD + 4 * lane];
            float a = sEA[r];
            acc.x = fmaf(a, w.x, acc.x);
            acc.y = fmaf(a, w.y, acc.y);
            acc.z = fmaf(a, w.z, acc.z);
            acc.w = fmaf(a, w.w, acc.w);
        }
        float4 bv = *(float4*)&sB[4 * lane];
        __half2* p = (__half2*)&g_tbln_h[(size_t)t * HD + 4 * lane];
        p[0] = __floats2half2_rn((acc.x + bv.x) * C, (acc.y + bv.y) * C);
        p[1] = __floats2half2_rn((acc.z + bv.z) * C, (acc.w + bv.w) * C);
    } else if (b < 274) {
        // ---- pad-convert one 128x128 weight to fp16 ----
        int mi = b - 256;   // 0..17
        const float* src;
        if (mi == 17) src = convW1;
        else {
            int l = mi / 3, j = mi % 3;
            src = (j == 0) ? convW2 + (size_t)l * 16384
                : (j == 1) ? linW + (size_t)l * 16384
                           : convW1 + (size_t)(l + 1) * 16384;
        }
        __half* dst = g_wt + (size_t)mi * WSLOT;
        for (int idx = tid; idx < 16384; idx += 512) {
            int k = idx >> 7, n = idx & 127;
            dst[k * PH + n] = __float2half(src[idx]);
        }
    } else if (b < 276) {
        // ---- pad-convert ncombW ----
        int halfsel = b - 274;
        for (int i = tid; i < 16384; i += 512) {
            int idx = halfsel * 16384 + i;
            int k = idx >> 7, n = idx & 127;
            g_wc[k * PH + n] = __float2half(ncombW[idx]);
        }
    } else if (b < 476) {
        // ---- embed ----
        for (int idx = (b - 276) * 512 + tid; idx < NA * HD; idx += 200 * 512) {
            int i = idx >> 7, h = idx & 127;
            int zz = z[i];
            g_x[idx] = emb[(size_t)zz * HD + h];
            g_yh[idx] = __float2half(nemb[(size_t)zz * HD + h]);
        }
    } else {
        // ---- geom count ----
        int e = (b - 476) * 512 + tid;
        if (e >= NE) return;
        int s = ei[e], d = ei[NE + e];
        float dx = pos[3 * s + 0] - pos[3 * d + 0];
        float dy = pos[3 * s + 1] - pos[3 * d + 1];
        float dz = pos[3 * s + 2] - pos[3 * d + 2];
        float d2 = dx * dx + dy * dy + dz * dz + 1e-12f;
        if (d2 < CUTR * CUTR) {
            g_tmp[e] = expf(-sqrtf(d2));
            atomicAdd(&g_cnt[d], 1);
        } else g_tmp[e] = -1.f;
    }
}

// ---------------- scan ----------------
__global__ void scan_kernel() {
    __shared__ int sh[1024];
    int tid = threadIdx.x;
    int base = tid * 10;
    int loc[10];
    int sum = 0;
    #pragma unroll
    for (int k = 0; k < 10; k++) {
        int i = base + k;
        int c = (i < NA) ? g_cnt[i] : 0;
        loc[k] = sum; sum += c;
    }
    sh[tid] = sum;
    __syncthreads();
    for (int off = 1; off < 1024; off <<= 1) {
        int v = 0;
        if (tid >= off) v = sh[tid - off];
        __syncthreads();
        sh[tid] += v;
        __syncthreads();
    }
    int pre = (tid == 0) ? 0 : sh[tid - 1];
    #pragma unroll
    for (int k = 0; k < 10; k++) {
        int i = base + k;
        if (i < NA) { g_off[i] = pre + loc[k]; g_cur[i] = pre + loc[k]; }
    }
    if (tid == 1023) g_off[NA] = sh[1023];
}

// ---------------- CSR fill ----------------
__global__ __launch_bounds__(512)
void geom_fill(const int* __restrict__ ei) {
    int e = blockIdx.x * 512 + threadIdx.x;
    if (e >= NE) return;
    float u = g_tmp[e];
    if (u >= 0.f) {
        int d = ei[NE + e];
        int j = atomicAdd(&g_cur[d], 1);
        g_edge[j] = make_int2(ei[e], __float_as_int(u));
    }
}

// ---------------- scatter v3: half-warp per edge, uint4 loads ----------------
__device__ __forceinline__ void edge_acc16(int j, int n, int hl, int self_mask,
        const __half* __restrict__ TBL, const __half* __restrict__ Y, float* acc) {
    int2 ed = __ldg(&g_edge[j]);
    int s = ed.x;
    float u = __int_as_float(ed.y);
    float tf = fminf(fmaxf((u - UMINF) * SCALEF, 0.f), (float)(NT - 1));
    int ti = (int)tf;
    if (ti > NT - 2) ti = NT - 2;
    float fr = tf - (float)ti;
    float g = (self_mask && (s == n)) ? 0.f : 1.f;
    const uint4* r0 = (const uint4*)TBL + (size_t)ti * 16 + hl;
    uint4 h0 = __ldg(r0);
    uint4 h1 = __ldg(r0 + 16);
    uint4 hy = __ldg((const uint4*)Y + (size_t)s * 16 + hl);
    __half2 fr2 = __float2half2_rn(fr);
    unsigned A[4] = {h0.x, h0.y, h0.z, h0.w};
    unsigned B[4] = {h1.x, h1.y, h1.z, h1.w};
    unsigned Yv[4] = {hy.x, hy.y, hy.z, hy.w};
    #pragma unroll
    for (int q = 0; q < 4; q++) {
        __half2 a2 = *(__half2*)&A[q];
        __half2 b2 = *(__half2*)&B[q];
        __half2 y2 = *(__half2*)&Yv[q];
        __half2 w = __hfma2(fr2, __hsub2(b2, a2), a2);
        __half2 p = __hmul2(w, y2);
        float2 f = __half22float2(p);
        acc[2 * q]     = fmaf(f.x, g, acc[2 * q]);
        acc[2 * q + 1] = fmaf(f.y, g, acc[2 * q + 1]);
    }
}

__global__ __launch_bounds__(256)
void scatter_kernel(const __half* __restrict__ TBL, const __half* __restrict__ Y,
                    float* __restrict__ M, int self_mask) {
    int warp = threadIdx.x >> 5, lane = threadIdx.x & 31;
    int hw = lane >> 4, hl = lane & 15;
    int n = blockIdx.x * 8 + warp;
    if (n >= NA) return;
    int beg = __ldg(&g_off[n]), end = __ldg(&g_off[n + 1]);
    float a0[8] = {0.f, 0.f, 0.f, 0.f, 0.f, 0.f, 0.f, 0.f};
    float a1[8] = {0.f, 0.f, 0.f, 0.f, 0.f, 0.f, 0.f, 0.f};
    int j = beg + hw;
    for (; j + 2 < end; j += 4) {
        edge_acc16(j, n, hl, self_mask, TBL, Y, a0);
        edge_acc16(j + 2, n, hl, self_mask, TBL, Y, a1);
    }
    if (j < end) edge_acc16(j, n, hl, self_mask, TBL, Y, a0);
    #pragma unroll
    for (int q = 0; q < 8; q++) a0[q] += a1[q];
    #pragma unroll
    for (int q = 0; q < 8; q++) a0[q] += __shfl_xor_sync(0xffffffffu, a0[q], 16);
    if (hw == 0) {
        *(float4*)(M + (size_t)n * HD + hl * 8) =
            make_float4(a0[0], a0[1], a0[2], a0[3]);
        *(float4*)(M + (size_t)n * HD + hl * 8 + 4) =
            make_float4(a0[4], a0[5], a0[6], a0[7]);
    }
}

// ================= mma.sync building blocks =================
__device__ __forceinline__ void mma_gemm(uint32_t aBase, int ksteps, uint32_t wBase, float* c) {
    #pragma unroll 2
    for (int k = 0; k < ksteps; k++) {
        uint32_t a0, a1, a2, a3;
        asm volatile("ldmatrix.sync.aligned.m8n8.x4.shared.b16 {%0,%1,%2,%3}, [%4];"
            : "=r"(a0), "=r"(a1), "=r"(a2), "=r"(a3) : "r"(aBase + k * 32));
        #pragma unroll
        for (int nbp = 0; nbp < 8; nbp++) {
            uint32_t b0, b1, b2r, b3;
            asm volatile("ldmatrix.sync.aligned.m8n8.x4.trans.shared.b16 {%0,%1,%2,%3}, [%4];"
                : "=r"(b0), "=r"(b1), "=r"(b2r), "=r"(b3)
                : "r"(wBase + k * (16 * 272) + nbp * 32));
            float* cp = c + nbp * 8;
            asm volatile("mma.sync.aligned.m16n8k16.row.col.f32.f16.f16.f32 "
                "{%0,%1,%2,%3}, {%4,%5,%6,%7}, {%8,%9}, {%0,%1,%2,%3};"
                : "+f"(cp[0]), "+f"(cp[1]), "+f"(cp[2]), "+f"(cp[3])
                : "r"(a0), "r"(a1), "r"(a2), "r"(a3), "r"(b0), "r"(b1));
            asm volatile("mma.sync.aligned.m16n8k16.row.col.f32.f16.f16.f32 "
                "{%0,%1,%2,%3}, {%4,%5,%6,%7}, {%8,%9}, {%0,%1,%2,%3};"
                : "+f"(cp[4]), "+f"(cp[5]), "+f"(cp[6]), "+f"(cp[7])
                : "r"(a0), "r"(a1), "r"(a2), "r"(a3), "r"(b2r), "r"(b3));
        }
    }
}

// ================= fused3 via mma.sync =================
__global__ __launch_bounds__(256, 1)
void fused3_mma(const float* __restrict__ M, const __half* __restrict__ WT,
                const float* __restrict__ b2, const float* __restrict__ bL,
                const float* __restrict__ X,
                float* __restrict__ xout, __half* __restrict__ yout, int has3) {
    extern __shared__ char smc[];
    uint32_t sb = smem_u32(smc);
    float* sBias = (float*)(smc + 139264);
    int tid = threadIdx.x, lane = tid & 31, warp = tid >> 5;
    int nw = has3 ? 3 : 2;
    {
        const uint4* ws = (const uint4*)WT;
        uint4* wd = (uint4*)(smc + 34816);
        for (int i = tid; i < nw * 2176; i += 256) wd[i] = ws[i];
    }
    if (tid < 128) { sBias[tid] = b2[tid]; sBias[128 + tid] = bL[tid]; }
    {
        int row = tid >> 1, sel = tid & 1;
        int node = min(blockIdx.x * 128 + row, NA - 1);
        const float4* src = (const float4*)(M + (size_t)node * HD) + sel * 16;
        uint4* dst = (uint4*)(smc + row * 272 + sel * 128);
        #pragma unroll
        for (int i = 0; i < 8; i++) {
            float4 v0 = __ldg(src + 2 * i), v1 = __ldg(src + 2 * i + 1);
            __half2 h0 = __floats2half2_rn(v0.x, v0.y);
            __half2 h1 = __floats2half2_rn(v0.z, v0.w);
            __half2 h2 = __floats2half2_rn(v1.x, v1.y);
            __half2 h3 = __floats2half2_rn(v1.z, v1.w);
            uint4 st;
            st.x = *(unsigned*)&h0; st.y = *(unsigned*)&h1;
            st.z = *(unsigned*)&h2; st.w = *(unsigned*)&h3;
            dst[i] = st;
        }
    }
    __syncthreads();

    int r0 = warp * 16;
    uint32_t aBase = sb + (r0 + (lane & 15)) * 272 + (lane >> 4) * 16;
    uint32_t bOff = ((lane & 7) + ((lane >> 3) & 1) * 8) * 272 + (lane >> 4) * 16;
    int cx = (lane & 3) * 2;
    int rtl = r0 + (lane >> 2);
    int nodeT = blockIdx.x * 128 + rtl;
    int nodeB = nodeT + 8;
    int nT = min(nodeT, NA - 1), nB = min(nodeB, NA - 1);
    float c[64];

    #pragma unroll
    for (int nb = 0; nb < 16; nb++) {
        float bx0 = sBias[nb * 8 + cx], bx1 = sBias[nb * 8 + cx + 1];
        c[nb * 4 + 0] = bx0; c[nb * 4 + 1] = bx1; c[nb * 4 + 2] = bx0; c[nb * 4 + 3] = bx1;
    }
    mma_gemm(aBase, 8, sb + 34816 + bOff, c);
    __syncwarp();
    #pragma unroll
    for (int nb = 0; nb < 16; nb++) {
        int col = nb * 8 + cx;
        *(__half2*)(smc + rtl * 272 + col * 2) =
            __floats2half2_rn(silu_f(c[nb * 4 + 0]), silu_f(c[nb * 4 + 1]));
        *(__half2*)(smc + (rtl + 8) * 272 + col * 2) =
            __floats2half2_rn(silu_f(c[nb * 4 + 2]), silu_f(c[nb * 4 + 3]));
    }
    __syncwarp();

    #pragma unroll
    for (int nb = 0; nb < 16; nb++) {
        float bx0 = sBias[128 + nb * 8 + cx], bx1 = sBias[128 + nb * 8 + cx + 1];
        c[nb * 4 + 0] = bx0; c[nb * 4 + 1] = bx1; c[nb * 4 + 2] = bx0; c[nb * 4 + 3] = bx1;
    }
    mma_gemm(aBase, 8, sb + 34816 + 34816 + bOff, c);
    __syncwarp();
    #pragma unroll
    for (int nb = 0; nb < 16; nb++) {
        int col = nb * 8 + cx;
        float2 xT = *(const float2*)(X + (size_t)nT * HD + col);
        float2 xB = *(const float2*)(X + (size_t)nB * HD + col);
        float vT0 = c[nb * 4 + 0] + xT.x, vT1 = c[nb * 4 + 1] + xT.y;
        float vB0 = c[nb * 4 + 2] + xB.x, vB1 = c[nb * 4 + 3] + xB.y;
        if (nodeT < NA) *(float2*)(xout + (size_t)nodeT * HD + col) = make_float2(vT0, vT1);
        if (nodeB < NA) *(float2*)(xout + (size_t)nodeB * HD + col) = make_float2(vB0, vB1);
        if (has3) {
            *(__half2*)(smc + rtl * 272 + col * 2) = __floats2half2_rn(vT0, vT1);
            *(__half2*)(smc + (rtl + 8) * 272 + col * 2) = __floats2half2_rn(vB0, vB1);
        }
    }
    if (!has3) return;
    __syncwarp();

    #pragma unroll
    for (int i = 0; i < 64; i++) c[i] = 0.f;
    mma_gemm(aBase, 8, sb + 34816 + 69632 + bOff, c);
    #pragma unroll
    for (int nb = 0; nb < 16; nb++) {
        int col = nb * 8 + cx;
        if (nodeT < NA)
            *(__half2*)(yout + (size_t)nodeT * HD + col) =
                __floats2half2_rn(c[nb * 4 + 0], c[nb * 4 + 1]);
        if (nodeB < NA)
            *(__half2*)(yout + (size_t)nodeB * HD + col) =
                __floats2half2_rn(c[nb * 4 + 2], c[nb * 4 + 3]);
    }
}

// ================= comb via mma.sync =================
__global__ __launch_bounds__(256, 1)
void comb_mma(const __half* __restrict__ Wc, const __half* __restrict__ W1,
              const float* __restrict__ bc) {
    extern __shared__ char smc[];
    uint32_t sb = smem_u32(smc);
    float* sBias = (float*)(smc + 172032);
    int tid = threadIdx.x, lane = tid & 31, warp = tid >> 5;
    {
        const uint4* ws = (const uint4*)Wc;
        uint4* wd = (uint4*)(smc + 67584);
        for (int i = tid; i < 4352; i += 256) wd[i] = ws[i];
        const uint4* w1s = (const uint4*)W1;
        uint4* w1d = (uint4*)(smc + 137216);
        for (int i = tid; i < 2176; i += 256) w1d[i] = w1s[i];
    }
    if (tid < 128) sBias[tid] = bc[tid];
    {
        int row = tid >> 1, sel = tid & 1;
        int node = min(blockIdx.x * 128 + row, NA - 1);
        const float4* src = sel ? (const float4*)(g_msg + (size_t)node * HD)
                                : (const float4*)(g_x + (size_t)node * HD);
        uint4* dst = (uint4*)(smc + row * 528 + sel * 256);
        #pragma unroll
        for (int i = 0; i < 16; i++) {
            float4 v0 = __ldg(src + 2 * i), v1 = __ldg(src + 2 * i + 1);
            __half2 h0 = __floats2half2_rn(v0.x, v0.y);
            __half2 h1 = __floats2half2_rn(v0.z, v0.w);
            __half2 h2 = __floats2half2_rn(v1.x, v1.y);
            __half2 h3 = __floats2half2_rn(v1.z, v1.w);
            uint4 st;
            st.x = *(unsigned*)&h0; st.y = *(unsigned*)&h1;
            st.z = *(unsigned*)&h2; st.w = *(unsigned*)&h3;
            dst[i] = st;
        }
    }
    __syncthreads();

    int r0 = warp * 16;
    uint32_t aBase = sb + (r0 + (lane & 15)) * 528 + (lane >> 4) * 16;
    uint32_t bOff = ((lane & 7) + ((lane >> 3) & 1) * 8) * 272 + (lane >> 4) * 16;
    int cx = (lane & 3) * 2;
    int rtl = r0 + (lane >> 2);
    int nodeT = blockIdx.x * 128 + rtl;
    int nodeB = nodeT + 8;
    float c[64];

    #pragma unroll
    for (int nb = 0; nb < 16; nb++) {
        float bx0 = sBias[nb * 8 + cx], bx1 = sBias[nb * 8 + cx + 1];
        c[nb * 4 + 0] = bx0; c[nb * 4 + 1] = bx1; c[nb * 4 + 2] = bx0; c[nb * 4 + 3] = bx1;
    }
    mma_gemm(aBase, 16, sb + 67584 + bOff, c);
    __syncwarp();
    #pragma unroll
    for (int nb = 0; nb < 16; nb++) {
        int col = nb * 8 + cx;
        float vT0 = c[nb * 4 + 0], vT1 = c[nb * 4 + 1];
        float vB0 = c[nb * 4 + 2], vB1 = c[nb * 4 + 3];
        if (nodeT < NA) *(float2*)(g_x + (size_t)nodeT * HD + col) = make_float2(vT0, vT1);
        if (nodeB < NA) *(float2*)(g_x + (size_t)nodeB * HD + col) = make_float2(vB0, vB1);
        *(__half2*)(smc + rtl * 528 + col * 2) = __floats2half2_rn(vT0, vT1);
        *(__half2*)(smc + (rtl + 8) * 528 + col * 2) = __floats2half2_rn(vB0, vB1);
    }
    __syncwarp();

    #pragma unroll
    for (int i = 0; i < 64; i++) c[i] = 0.f;
    mma_gemm(aBase, 8, sb + 137216 + bOff, c);
    #pragma unroll
    for (int nb = 0; nb < 16; nb++) {
        int col = nb * 8 + cx;
        if (nodeT < NA)
            *(__half2*)(g_yh + (size_t)nodeT * HD + col) =
                __floats2half2_rn(c[nb * 4 + 0], c[nb * 4 + 1]);
        if (nodeB < NA)
            *(__half2*)(g_yh + (size_t)nodeB * HD + col) =
                __floats2half2_rn(c[nb * 4 + 2], c[nb * 4 + 3]);
    }
}

// ---------------- launcher ----------------
extern "C" void kernel_launch(void* const* d_in, const int* in_sizes, int n_in,
                              void* d_out, int out_size) {
    const int*   z      = (const int*)d_in[0];
    const float* pos    = (const float*)d_in[1];
    const int*   ei     = (const int*)d_in[3];
    const float* emb    = (const float*)d_in[4];
    const float* nemb   = (const float*)d_in[5];
    const float* nprojW = (const float*)d_in[6];
    const float* nprojB = (const float*)d_in[7];
    const float* ncombW = (const float*)d_in[8];
    const float* ncombB = (const float*)d_in[9];
    const float* means  = (const float*)d_in[10];
    const float* betas  = (const float*)d_in[11];
    const float* mlpW1  = (const float*)d_in[12];
    const float* mlpb1  = (const float*)d_in[13];
    const float* mlpW2  = (const float*)d_in[14];
    const float* mlpb2  = (const float*)d_in[15];
    const float* convW1 = (const float*)d_in[16];
    const float* convW2 = (const float*)d_in[17];
    const float* convb2 = (const float*)d_in[18];
    const float* linW   = (const float*)d_in[19];
    const float* linb   = (const float*)d_in[20];
    float* out = (float*)d_out;

    void *p_cnt, *p_x, *p_yh, *p_m, *p_msg, *p_tc, *p_tn, *p_wt, *p_wc;
    cudaGetSymbolAddress(&p_cnt, g_cnt);
    cudaGetSymbolAddress(&p_x, g_x);
    cudaGetSymbolAddress(&p_yh, g_yh);
    cudaGetSymbolAddress(&p_m, g_m);
    cudaGetSymbolAddress(&p_msg, g_msg);
    cudaGetSymbolAddress(&p_tc, g_tblcf_h);
    cudaGetSymbolAddress(&p_tn, g_tbln_h);
    cudaGetSymbolAddress(&p_wt, g_wt);
    cudaGetSymbolAddress(&p_wc, g_wc);
    float* px = (float*)p_x;
    __half* pyh = (__half*)p_yh;
    float* pm = (float*)p_m;
    float* pmsg = (float*)p_msg;
    __half* ptc = (__half*)p_tc;
    __half* ptn = (__half*)p_tn;
    __half* pwt = (__half*)p_wt;
    __half* pwc = (__half*)p_wc;

    size_t sh_mega = (size_t)28992 * sizeof(float);
    size_t sh_f3m  = 140288;
    size_t sh_cmm  = 172544;
    cudaFuncSetAttribute(mega_setup, cudaFuncAttributeMaxDynamicSharedMemorySize, (int)sh_mega);
    cudaFuncSetAttribute(fused3_mma, cudaFuncAttributeMaxDynamicSharedMemorySize, (int)sh_f3m);
    cudaFuncSetAttribute(comb_mma,   cudaFuncAttributeMaxDynamicSharedMemorySize, (int)sh_cmm);

    cudaMemsetAsync(p_cnt, 0, NA * sizeof(int));
    mega_setup<<<1101, 512, sh_mega>>>(ei, pos, z, emb, nemb, means, betas,
                                       nprojW, nprojB, mlpW1, mlpb1, mlpW2, mlpb2,
                                       convW1, convW2, linW, ncombW);
    scan_kernel<<<1, 1024>>>();
    geom_fill<<<625, 512>>>(ei);
    scatter_kernel<<<(NA + 7) / 8, 256>>>(ptn, pyh, pmsg, 1);
    comb_mma<<<NBLK79, 256, sh_cmm>>>(pwc, pwt + (size_t)17 * WSLOT, ncombB);

    for (int l = 0; l < NL; l++) {
        scatter_kernel<<<(NA + 7) / 8, 256>>>(ptc + (size_t)l * NT * HD, pyh, pm, 0);
        float* dest = (l == NL - 1) ? out : px;
        fused3_mma<<<NBLK79, 256, sh_f3m>>>(pm, pwt + (size_t)(l * 3) * WSLOT,
                                            convb2 + (size_t)l * HD,
                                            linb + (size_t)l * HD,
                                            px, dest, pyh, (l < NL - 1) ? 1 : 0);
    }
}